// round 2
// baseline (speedup 1.0000x reference)
#include <cuda_runtime.h>
#include <cuda_bf16.h>

// ALiBi bias materialization:
//   out[z, i, j] = -slopes[z % 16] * |i - j|,  z in [0,64), i,j in [0,2048)
// Output 1 GiB fp32 -> pure HBM-write-bound.
//
// R2: fatter blocks. Each block covers 4 consecutive rows (4 | 2048 so the
// head h = (row>>11)&15 is uniform within a block). Each thread issues 8
// independent STG.128 (2 per row x 4 rows) for high store MLP; grid shrinks
// 262144 -> 32768.

#define S        2048
#define NUM_H    16
#define Z_TOTAL  64
#define THREADS  256
#define ROWS_PER_BLOCK 4

__global__ __launch_bounds__(THREADS)
void alibi_kernel(const float* __restrict__ slopes, float* __restrict__ out) {
    const unsigned bx      = blockIdx.x;
    const unsigned row0    = bx * ROWS_PER_BLOCK;          // first of 4 rows
    const unsigned h       = (row0 >> 11) & (NUM_H - 1);   // uniform in block

    const float neg_slope = -__ldg(&slopes[h]);

    const unsigned t  = threadIdx.x;
    const unsigned jA = t * 4u;          // first half-row position
    const unsigned jB = jA + 1024u;      // second half-row position
    const float fjA = (float)jA;
    const float fjB = (float)jB;

    float* base = out + (size_t)row0 * S;

#pragma unroll
    for (int r = 0; r < ROWS_PER_BLOCK; r++) {
        const float fi = (float)((row0 + r) & (S - 1));

        float4 a, b;
        a.x = neg_slope * fabsf(fi - fjA);
        a.y = neg_slope * fabsf(fi - (fjA + 1.0f));
        a.z = neg_slope * fabsf(fi - (fjA + 2.0f));
        a.w = neg_slope * fabsf(fi - (fjA + 3.0f));
        b.x = neg_slope * fabsf(fi - fjB);
        b.y = neg_slope * fabsf(fi - (fjB + 1.0f));
        b.z = neg_slope * fabsf(fi - (fjB + 2.0f));
        b.w = neg_slope * fabsf(fi - (fjB + 3.0f));

        float* rowp = base + (size_t)r * S;
        reinterpret_cast<float4*>(rowp)[t]        = a;
        reinterpret_cast<float4*>(rowp + 1024)[t] = b;
    }
}

extern "C" void kernel_launch(void* const* d_in, const int* in_sizes, int n_in,
                              void* d_out, int out_size) {
    const float* slopes = (const float*)d_in[0];
    float* out = (float*)d_out;

    const unsigned grid = (Z_TOTAL * S) / ROWS_PER_BLOCK;   // 32768
    alibi_kernel<<<grid, THREADS>>>(slopes, out);
}

// round 3
// speedup vs baseline: 1.0004x; 1.0004x over previous
#include <cuda_runtime.h>
#include <cuda_bf16.h>

// ALiBi bias materialization:
//   out[z, i, j] = -slopes[z % 16] * |i - j|,  z in [0,64), i,j in [0,2048)
// Output 1 GiB fp32 -> pure HBM-write-bound (measured wall ~7.0 TB/s).
//
// R3: streaming stores (st.global.cs, evict-first) so dirty L2 lines drain
// to DRAM promptly instead of lazy eviction; all 8 STG.128 issued
// back-to-back after value computation.

#define S        2048
#define NUM_H    16
#define Z_TOTAL  64
#define THREADS  256
#define ROWS_PER_BLOCK 4

__global__ __launch_bounds__(THREADS)
void alibi_kernel(const float* __restrict__ slopes, float* __restrict__ out) {
    const unsigned bx   = blockIdx.x;
    const unsigned row0 = bx * ROWS_PER_BLOCK;           // first of 4 rows
    const unsigned h    = (row0 >> 11) & (NUM_H - 1);    // uniform in block

    const float neg_slope = -__ldg(&slopes[h]);

    const unsigned t  = threadIdx.x;
    const unsigned jA = t * 4u;
    const unsigned jB = jA + 1024u;
    const float fjA = (float)jA;
    const float fjB = (float)jB;

    float* base = out + (size_t)row0 * S;

    float4 v[ROWS_PER_BLOCK][2];
#pragma unroll
    for (int r = 0; r < ROWS_PER_BLOCK; r++) {
        const float fi = (float)((row0 + r) & (S - 1));
        v[r][0].x = neg_slope * fabsf(fi - fjA);
        v[r][0].y = neg_slope * fabsf(fi - (fjA + 1.0f));
        v[r][0].z = neg_slope * fabsf(fi - (fjA + 2.0f));
        v[r][0].w = neg_slope * fabsf(fi - (fjA + 3.0f));
        v[r][1].x = neg_slope * fabsf(fi - fjB);
        v[r][1].y = neg_slope * fabsf(fi - (fjB + 1.0f));
        v[r][1].z = neg_slope * fabsf(fi - (fjB + 2.0f));
        v[r][1].w = neg_slope * fabsf(fi - (fjB + 3.0f));
    }

#pragma unroll
    for (int r = 0; r < ROWS_PER_BLOCK; r++) {
        float* rowp = base + (size_t)r * S;
        __stcs(reinterpret_cast<float4*>(rowp) + t,          v[r][0]);
        __stcs(reinterpret_cast<float4*>(rowp + 1024) + t,   v[r][1]);
    }
}

extern "C" void kernel_launch(void* const* d_in, const int* in_sizes, int n_in,
                              void* d_out, int out_size) {
    const float* slopes = (const float*)d_in[0];
    float* out = (float*)d_out;

    const unsigned grid = (Z_TOTAL * S) / ROWS_PER_BLOCK;   // 32768
    alibi_kernel<<<grid, THREADS>>>(slopes, out);
}

// round 4
// speedup vs baseline: 1.0011x; 1.0007x over previous
#include <cuda_runtime.h>
#include <cuda_bf16.h>

// ALiBi bias materialization:
//   out[z, i, j] = -slopes[z % 16] * |i - j|,  z in [0,64), i,j in [0,2048)
// Output 1 GiB fp32 -> pure HBM-write-bound (measured wall ~7.0 TB/s).
//
// R4: sm_100a 256-bit stores (st.global.v8.f32). Each thread writes 32
// contiguous bytes per row (j = t*8 .. t*8+7); one warp instruction covers
// 1 KiB. Tests whether wider store granularity improves DRAM burst
// formation; everything upstream (issue, occ, L2) has slack.

#define S        2048
#define NUM_H    16
#define Z_TOTAL  64
#define THREADS  256           // 256 threads * 8 floats = 2048 = one full row
#define ROWS_PER_BLOCK 4

__device__ __forceinline__ void stg256(float* p, const float v[8]) {
    asm volatile(
        "st.global.v8.f32 [%0], {%1, %2, %3, %4, %5, %6, %7, %8};"
        :: "l"(p),
           "f"(v[0]), "f"(v[1]), "f"(v[2]), "f"(v[3]),
           "f"(v[4]), "f"(v[5]), "f"(v[6]), "f"(v[7])
        : "memory");
}

__global__ __launch_bounds__(THREADS)
void alibi_kernel(const float* __restrict__ slopes, float* __restrict__ out) {
    const unsigned bx   = blockIdx.x;
    const unsigned row0 = bx * ROWS_PER_BLOCK;           // first of 4 rows
    const unsigned h    = (row0 >> 11) & (NUM_H - 1);    // uniform in block

    const float neg_slope = -__ldg(&slopes[h]);

    const unsigned t  = threadIdx.x;
    const unsigned j0 = t * 8u;                          // 32B contiguous
    const float fj0 = (float)j0;

    float* base = out + (size_t)row0 * S + j0;

#pragma unroll
    for (int r = 0; r < ROWS_PER_BLOCK; r++) {
        const float fi = (float)((row0 + r) & (S - 1));

        float v[8];
#pragma unroll
        for (int k = 0; k < 8; k++)
            v[k] = neg_slope * fabsf(fi - (fj0 + (float)k));

        stg256(base + (size_t)r * S, v);
    }
}

extern "C" void kernel_launch(void* const* d_in, const int* in_sizes, int n_in,
                              void* d_out, int out_size) {
    const float* slopes = (const float*)d_in[0];
    float* out = (float*)d_out;

    const unsigned grid = (Z_TOTAL * S) / ROWS_PER_BLOCK;   // 32768
    alibi_kernel<<<grid, THREADS>>>(slopes, out);
}